// round 16
// baseline (speedup 1.0000x reference)
#include <cuda_runtime.h>
#include <cuda_fp16.h>
#include <cstdint>

// Fused GAT network on mma.sync.m16n8k16 (A fp16, B fp16, fp32 accum).
// 8 graphs per 512-thread block: M = 128, N = 256, K = FIN.
// R16: triple-buffered B staging (3 syncs per 4-chunk layer instead of 4)
// + attention vectors staged once for all layers.

#define NN 16
#define ASTRB 528         // A row stride bytes (264 halves)
#define BSTRB 144         // B chunk row stride bytes (72 halves)
#define BBYTES 36864      // one B chunk buffer

// ---- shared memory byte offsets ----
#define OFF_A     0            // fp16 A tile 128 x 264 (67584 B)
#define OFF_B0    67584        // B buffers 0,1,2 contiguous (3 x 36864 = 110592)
#define OFF_ALPHA 67584        // alpha fp16 planes: 32 x 784 B (overlays B0)
#define OFF_ASRC  178176       // 3 layers x 1024 B
#define OFF_ADST  181248       // 3 layers x 1024 B
#define OFF_WSCR  184320       // 4096 B: 16 warps x 64 floats
#define OFF_G4    188416       // 8192 B (FINAL only)
#define OFF_XS    188416       // x staging 8192 B overlays G4 (pre-layer0)
#define OFF_G     196608       // 2048 B
#define OFF_Y     198656       // 4224 B
#define OFF_RED   202880       // 256 B
#define SMEM_BYTES 203136

// transposed fp16 weights WT[n][k]: W0 16384, W1 65536, W2 65536 elems
__device__ __align__(16) __half g_WTh[147456];

__device__ __forceinline__ uint32_t smem_u32(const void* p) {
    uint32_t a;
    asm("{ .reg .u64 t; cvta.to.shared.u64 t, %1; cvt.u32.u64 %0, t; }" : "=r"(a) : "l"(p));
    return a;
}

#define LDSM4(r, a) \
    asm volatile("ldmatrix.sync.aligned.m8n8.x4.shared.b16 {%0,%1,%2,%3}, [%4];" \
        : "=r"((r)[0]), "=r"((r)[1]), "=r"((r)[2]), "=r"((r)[3]) : "r"(a))

#define MOVM(dst, src) \
    asm volatile("movmatrix.sync.aligned.m8n8.trans.b16 %0, %1;" \
        : "=r"(dst) : "r"(src))

#define MMA16816F(d, a, b0, b1) \
    asm volatile("mma.sync.aligned.m16n8k16.row.col.f32.f16.f16.f32 " \
        "{%0,%1,%2,%3}, {%4,%5,%6,%7}, {%8,%9}, {%0,%1,%2,%3};" \
        : "+f"((d)[0]), "+f"((d)[1]), "+f"((d)[2]), "+f"((d)[3]) \
        : "r"((a)[0]), "r"((a)[1]), "r"((a)[2]), "r"((a)[3]), "r"(b0), "r"(b1))

#define CP_ASYNC16(dst, src) \
    asm volatile("cp.async.cg.shared.global [%0], [%1], 16;" :: "r"(dst), "l"(src))
#define CP_COMMIT() asm volatile("cp.async.commit_group;" ::: "memory")
#define CP_WAIT0()  asm volatile("cp.async.wait_group 0;" ::: "memory")

__device__ __forceinline__ unsigned adjmask(int i) {
    int r = i >> 2, c = i & 3;
    unsigned m = 1u << i;
    if (c > 0) m |= 1u << (i - 1);
    if (c < 3) m |= 1u << (i + 1);
    if (r > 0) m |= 1u << (i - 4);
    if (r < 3) m |= 1u << (i + 4);
    return m;
}

// ---- weight prep: transpose + fp16 ----
__global__ void prep_kernel(const float* __restrict__ W0,
                            const float* __restrict__ W1,
                            const float* __restrict__ W2) {
    int i = blockIdx.x * 256 + threadIdx.x;
    if (i >= 147456) return;
    float v;
    if (i < 16384) {                       // WT0[n*64+k] = W0[k*256+n]
        int n = i >> 6, k = i & 63;
        v = W0[k * 256 + n];
    } else if (i < 81920) {                // WT1[n*256+k] = W1[k*256+n]
        int j = i - 16384; int n = j >> 8, k = j & 255;
        v = W1[k * 256 + n];
    } else {                               // WT2
        int j = i - 81920; int n = j >> 8, k = j & 255;
        v = W2[k * 256 + n];
    }
    g_WTh[i] = __float2half_rn(v);
}

// stage one 64-K chunk (64 B per thread) into buffer idx (0..2)
__device__ __forceinline__ void stage_chunk(uint32_t smb, uint32_t snoff,
                                            int bufIdx, const char* gsrc) {
    uint32_t dst = smb + OFF_B0 + (uint32_t)bufIdx * BBYTES + snoff;
    #pragma unroll
    for (int q = 0; q < 4; q++) CP_ASYNC16(dst + q * 16, gsrc + q * 16);
}

// ---- one GAT layer ----
// START = buffer index (0..2) holding prefetched chunk 0.
template<int FIN, int START, bool FINAL>
__device__ void gat_layer(char* smc, uint32_t smb, int tid,
                          const __half* __restrict__ WTh,
                          const float* __restrict__ as_s,   // smem, this layer
                          const float* __restrict__ ad_s,
                          const float* __restrict__ bb,
                          const __half* __restrict__ nextWT, int nextFIN)
{
    const int NCH = FIN / 64;
    const int wid = tid >> 5, l = tid & 31;
    const int wr2 = wid & 3;         // row block: items 2wr2, 2wr2+1
    const int cg4 = wid >> 2;        // head: cols 64*cg4 .. +63
    const int nb0 = cg4 * 64;

    uint32_t aAddr0 = smb + OFF_A + (uint32_t)((wr2 * 32 + (l & 15)) * ASTRB)
                    + (uint32_t)((l >> 4) * 16);
    uint32_t aAddr1 = aAddr0 + 16 * ASTRB;
    int bn = (l & 7) + ((l >> 4) << 3);
    uint32_t bLane = (uint32_t)((nb0 + bn) * BSTRB) + (uint32_t)(((l >> 3) & 1) * 16);

    const int sn = tid >> 1, shf = tid & 1;
    const char* gbase = (const char*)(WTh + sn * FIN + shf * 32);
    uint32_t snoff = (uint32_t)(sn * BSTRB + shf * 64);

    float d[2][8][4];
    #pragma unroll
    for (int rg = 0; rg < 2; rg++)
        #pragma unroll
        for (int nb = 0; nb < 8; nb++)
            #pragma unroll
            for (int q = 0; q < 4; q++) d[rg][nb][q] = 0.f;

    // one 4-kk chunk of MMAs from buffer at bufIdx, K offset k16base
    auto mma_chunk = [&](int bufIdx, int k16base) {
        uint32_t bufBase = smb + OFF_B0 + (uint32_t)bufIdx * BBYTES + bLane;
        #pragma unroll
        for (int kk = 0; kk < 4; kk++) {
            int k16 = k16base + kk;
            uint32_t a0[4], a1[4];
            LDSM4(a0, aAddr0 + k16 * 32);
            LDSM4(a1, aAddr1 + k16 * 32);
            #pragma unroll
            for (int nt = 0; nt < 4; nt++) {
                uint32_t ba = bufBase + nt * (16 * BSTRB) + kk * 32;
                uint32_t bh4[4];
                LDSM4(bh4, ba);
                MMA16816F(d[0][2 * nt],     a0, bh4[0], bh4[1]);
                MMA16816F(d[0][2 * nt + 1], a0, bh4[2], bh4[3]);
                MMA16816F(d[1][2 * nt],     a1, bh4[0], bh4[1]);
                MMA16816F(d[1][2 * nt + 1], a1, bh4[2], bh4[3]);
            }
        }
    };

    // entry: chunk 0 was prefetched; wait own copies + block-wide visibility.
    CP_WAIT0();
    __syncthreads();

    if (NCH == 1) {
        mma_chunk(START, 0);
        __syncthreads();    // all B/A reads done before alpha overlays B0
    } else {
        constexpr int BI0 = START;
        constexpr int BI1 = (START + 1) % 3;
        constexpr int BI2 = (START + 2) % 3;
        // it0: stage chunks 1 & 2, run chunk 0
        stage_chunk(smb, snoff, BI1, gbase + 1 * 128);
        stage_chunk(smb, snoff, BI2, gbase + 2 * 128);
        CP_COMMIT();
        mma_chunk(BI0, 0);
        CP_WAIT0();
        __syncthreads();
        // it1: stage chunk 3 into BI0 (readers of chunk0 are past end-it0 sync)
        stage_chunk(smb, snoff, BI0, gbase + 3 * 128);
        CP_COMMIT();
        mma_chunk(BI1, 4);
        // it2 (chunk 2 visible since end-it0 sync)
        mma_chunk(BI2, 8);
        CP_WAIT0();
        __syncthreads();
        // it3
        mma_chunk(BI0, 12);
        __syncthreads();    // all reads done before epilogue overwrites A/alpha
    }

    // ---- in-register logits from D-fragments (head = cg4), warp-local ----
    float* wsc = (float*)(smc + OFF_WSCR) + wid * 64;
    {
        float pS[2][2] = {{0.f,0.f},{0.f,0.f}};
        float pD[2][2] = {{0.f,0.f},{0.f,0.f}};
        const float* asp = as_s + cg4 * 64;
        const float* adp = ad_s + cg4 * 64;
        int cbase = (l & 3) * 2;
        #pragma unroll
        for (int nb = 0; nb < 8; nb++) {
            int c64 = nb * 8 + cbase;
            float2 av = *(const float2*)&asp[c64];
            float2 dv = *(const float2*)&adp[c64];
            #pragma unroll
            for (int rg = 0; rg < 2; rg++) {
                pS[rg][0] = fmaf(d[rg][nb][0], av.x, fmaf(d[rg][nb][1], av.y, pS[rg][0]));
                pS[rg][1] = fmaf(d[rg][nb][2], av.x, fmaf(d[rg][nb][3], av.y, pS[rg][1]));
                pD[rg][0] = fmaf(d[rg][nb][0], dv.x, fmaf(d[rg][nb][1], dv.y, pD[rg][0]));
                pD[rg][1] = fmaf(d[rg][nb][2], dv.x, fmaf(d[rg][nb][3], dv.y, pD[rg][1]));
            }
        }
        #pragma unroll
        for (int off = 1; off <= 2; off <<= 1) {
            #pragma unroll
            for (int rg = 0; rg < 2; rg++) {
                #pragma unroll
                for (int rh = 0; rh < 2; rh++) {
                    pS[rg][rh] += __shfl_xor_sync(0xffffffffu, pS[rg][rh], off);
                    pD[rg][rh] += __shfl_xor_sync(0xffffffffu, pD[rg][rh], off);
                }
            }
        }
        if ((l & 3) == 0) {
            int n1 = l >> 2;
            #pragma unroll
            for (int rg = 0; rg < 2; rg++) {
                #pragma unroll
                for (int rh = 0; rh < 2; rh++) {
                    wsc[rg * 32 + (n1 + 8 * rh)]      = pS[rg][rh];
                    wsc[rg * 32 + 16 + (n1 + 8 * rh)] = pD[rg][rh];
                }
            }
        }
    }
    __syncwarp();

    // ---- warp-local masked softmax: lane = (uloc = l>>4, i = l&15) ----
    {
        int uloc = l >> 4, i = l & 15;
        int u = wr2 * 2 + uloc;
        float ed = wsc[uloc * 32 + 16 + i];
        unsigned m = adjmask(i);
        float eb[NN];
        float mx = -1e30f;
        #pragma unroll
        for (int j = 0; j < NN; j++) {
            eb[j] = -1e30f;
            if ((m >> j) & 1u) {
                float e = ed + wsc[uloc * 32 + j];
                e = e > 0.f ? e : 0.2f * e;
                eb[j] = e;
                mx = fmaxf(mx, e);
            }
        }
        float ssum = 0.f;
        #pragma unroll
        for (int j = 0; j < NN; j++) {
            float a = ((m >> j) & 1u) ? __expf(eb[j] - mx) : 0.f;
            eb[j] = a;
            ssum += a;
        }
        float inv = 1.f / ssum;
        __half2 hp[8];
        #pragma unroll
        for (int j2 = 0; j2 < 8; j2++)
            hp[j2] = __floats2half2_rn(eb[2 * j2] * inv, eb[2 * j2 + 1] * inv);
        char* dst = smc + OFF_ALPHA + (u * 4 + cg4) * 784 + i * 48;
        uint4 w0, w1;
        w0.x = *(uint32_t*)&hp[0]; w0.y = *(uint32_t*)&hp[1];
        w0.z = *(uint32_t*)&hp[2]; w0.w = *(uint32_t*)&hp[3];
        w1.x = *(uint32_t*)&hp[4]; w1.y = *(uint32_t*)&hp[5];
        w1.z = *(uint32_t*)&hp[6]; w1.w = *(uint32_t*)&hp[7];
        *(uint4*)dst = w0;
        *(uint4*)(dst + 16) = w1;
    }
    __syncwarp();

    // ---- aggregation on tensor cores, fully warp-local (movmatrix B) ----
    #pragma unroll
    for (int rg = 0; rg < 2; rg++) {
        int u = wr2 * 2 + rg;
        uint32_t aA = smb + OFF_ALPHA
                    + (uint32_t)((u * 4 + cg4) * 784 + (l & 15) * 48 + (l >> 4) * 16);
        uint32_t af[4];
        LDSM4(af, aA);
        float ddag[8][4];
        #pragma unroll
        for (int nb = 0; nb < 8; nb++) {
            ddag[nb][0] = ddag[nb][1] = ddag[nb][2] = ddag[nb][3] = 0.f;
            __half2 h01 = __floats2half2_rn(d[rg][nb][0], d[rg][nb][1]);
            __half2 h23 = __floats2half2_rn(d[rg][nb][2], d[rg][nb][3]);
            uint32_t b0, b1;
            MOVM(b0, *(uint32_t*)&h01);
            MOVM(b1, *(uint32_t*)&h23);
            MMA16816F(ddag[nb], af, b0, b1);
        }
        if (FINAL) {
            #pragma unroll
            for (int nb = 0; nb < 8; nb++) {
                float pc0 = ddag[nb][0] + ddag[nb][2];
                float pc1 = ddag[nb][1] + ddag[nb][3];
                #pragma unroll
                for (int off = 4; off <= 16; off <<= 1) {
                    pc0 += __shfl_xor_sync(0xffffffffu, pc0, off);
                    pc1 += __shfl_xor_sync(0xffffffffu, pc1, off);
                }
                if (l < 4)
                    *(float2*)((float*)(smc + OFF_G4) + u * 256 + cg4 * 64 + nb * 8 + l * 2)
                        = make_float2(pc0, pc1);
            }
        } else {
            __half* ab = (__half*)(smc + OFF_A);
            int r0 = u * 16 + (l >> 2);
            #pragma unroll
            for (int nb = 0; nb < 8; nb++) {
                int cn = cg4 * 64 + nb * 8 + (l & 3) * 2;
                float2 bv = *(const float2*)&bb[cn];
                float v0 = fmaxf(ddag[nb][0] + bv.x, 0.f);
                float v1 = fmaxf(ddag[nb][1] + bv.y, 0.f);
                float v2 = fmaxf(ddag[nb][2] + bv.x, 0.f);
                float v3 = fmaxf(ddag[nb][3] + bv.y, 0.f);
                *(__half2*)&ab[r0 * 264 + cn]       = __floats2half2_rn(v0, v1);
                *(__half2*)&ab[(r0 + 8) * 264 + cn] = __floats2half2_rn(v2, v3);
            }
        }
    }
    // prefetch next layer's chunk 0 into buffer (START + NCH) % 3
    if (!FINAL) {
        constexpr int NSTART = (START + FIN / 64) % 3;
        const int psn = tid >> 1, pshf = tid & 1;
        stage_chunk(smb, (uint32_t)(psn * BSTRB + pshf * 64), NSTART,
                    (const char*)(nextWT + psn * nextFIN + pshf * 32));
        CP_COMMIT();
        // no sync: next layer's entry CP_WAIT0 + __syncthreads covers ordering
    } else {
        __syncthreads();
    }
}

__global__ void __launch_bounds__(512, 1) gat_mma_kernel(
    const float* __restrict__ x,
    const float* __restrict__ w_in, const float* __restrict__ b_in,
    const float* __restrict__ as0, const float* __restrict__ ad0,
    const float* __restrict__ bb0,
    const float* __restrict__ as1, const float* __restrict__ ad1,
    const float* __restrict__ bb1,
    const float* __restrict__ as2, const float* __restrict__ ad2,
    const float* __restrict__ bb2,
    const float* __restrict__ w1, const float* __restrict__ b1,
    const float* __restrict__ lng, const float* __restrict__ lnb,
    const float* __restrict__ w2, const float* __restrict__ b2,
    float* __restrict__ out)
{
    extern __shared__ char smc[];
    uint32_t smb = smem_u32(smc);
    int tid = threadIdx.x;
    long item0 = (long)blockIdx.x * 8;

    // prefetch layer 0's single B chunk into buffer 0
    {
        int sn = tid >> 1, shf = tid & 1;
        stage_chunk(smb, (uint32_t)(sn * BSTRB + shf * 64), 0,
                    (const char*)(g_WTh + sn * 64 + shf * 32));
        CP_COMMIT();
    }

    // stage x (overlays G4) + all 3 layers' attention vectors
    float* xs = (float*)(smc + OFF_XS);
    #pragma unroll
    for (int q = 0; q < 4; q++)
        xs[q * 512 + tid] = x[item0 * 256 + q * 512 + tid];
    {
        float* AS = (float*)(smc + OFF_ASRC);
        float* AD = (float*)(smc + OFF_ADST);
        if (tid < 256) {
            AS[tid]        = as0[tid];
            AS[256 + tid]  = as1[tid];
            AS[512 + tid]  = as2[tid];
        } else {
            int t2 = tid - 256;
            AD[t2]         = ad0[t2];
            AD[256 + t2]   = ad1[t2];
            AD[512 + t2]   = ad2[t2];
        }
    }
    __syncthreads();

    // input linear -> A (fp16), thread = (u = tid>>6, f = tid&63)
    {
        int u = tid >> 6, f = tid & 63;
        const float* xu = xs + u * 256;
        float acc[NN];
        #pragma unroll
        for (int nn = 0; nn < NN; nn++) acc[nn] = 0.f;
        #pragma unroll
        for (int c = 0; c < 16; c++) {
            float wv = w_in[c * 64 + f];
            #pragma unroll
            for (int nn = 0; nn < NN; nn++)
                acc[nn] = fmaf(xu[c * 16 + nn], wv, acc[nn]);
        }
        float bv = b_in[f];
        __half* ab = (__half*)(smc + OFF_A);
        #pragma unroll
        for (int nn = 0; nn < NN; nn++) {
            float vv = fmaxf(acc[nn] + bv, 0.f);
            ab[(u * 16 + nn) * 264 + f] = __float2half_rn(vv);
        }
    }
    // no sync: layer 0's entry CP_WAIT0 + __syncthreads orders A writes

    const float* AS = (const float*)(smc + OFF_ASRC);
    const float* AD = (const float*)(smc + OFF_ADST);
    gat_layer<64,  0, false>(smc, smb, tid, g_WTh,         AS,       AD,       bb0,
                             g_WTh + 16384, 256);
    gat_layer<256, 1, false>(smc, smb, tid, g_WTh + 16384, AS + 256, AD + 256, bb1,
                             g_WTh + 81920, 256);
    gat_layer<256, 2, true >(smc, smb, tid, g_WTh + 81920, AS + 512, AD + 512, bb2,
                             (const __half*)nullptr, 0);

    // pooled g[c] = mean over nodes+heads + bb2
    {
        int u = tid >> 6, cc = tid & 63;
        const float* g4 = (const float*)(smc + OFF_G4) + u * 256;
        float sg = g4[cc] + g4[64 + cc] + g4[128 + cc] + g4[192 + cc];
        ((float*)(smc + OFF_G))[u * 64 + cc] = sg * (1.0f / 64.0f) + bb2[cc];
    }
    __syncthreads();

    // MLP1 (64->128) + LN + relu; thread covers items up, up+4
    {
        int fy = tid & 127, up = tid >> 7;
        int ua = up, ub = up + 4;
        const float* ga_ = (const float*)(smc + OFF_G) + ua * 64;
        const float* gb_ = (const float*)(smc + OFF_G) + ub * 64;
        float va = b1[fy], vb = va;
        #pragma unroll 4
        for (int c = 0; c < 64; c += 4) {
            float4 ga = *(const float4*)&ga_[c];
            float4 gb = *(const float4*)&gb_[c];
            float w0 = w1[(c + 0) * 128 + fy];
            float wA = w1[(c + 1) * 128 + fy];
            float wB = w1[(c + 2) * 128 + fy];
            float wC = w1[(c + 3) * 128 + fy];
            va = fmaf(ga.x, w0, fmaf(ga.y, wA, fmaf(ga.z, wB, fmaf(ga.w, wC, va))));
            vb = fmaf(gb.x, w0, fmaf(gb.y, wA, fmaf(gb.z, wB, fmaf(gb.w, wC, vb))));
        }
        float* red = (float*)(smc + OFF_RED);
        float sa = va, sb = vb;
        #pragma unroll
        for (int off = 16; off; off >>= 1) {
            sa += __shfl_xor_sync(0xffffffffu, sa, off);
            sb += __shfl_xor_sync(0xffffffffu, sb, off);
        }
        int wi = (tid >> 5) & 3;
        if ((tid & 31) == 0) { red[ua * 8 + wi] = sa; red[ub * 8 + wi] = sb; }
        __syncthreads();
        float mua = (red[ua * 8] + red[ua * 8 + 1] + red[ua * 8 + 2] + red[ua * 8 + 3]) * (1.f / 128.f);
        float mub = (red[ub * 8] + red[ub * 8 + 1] + red[ub * 8 + 2] + red[ub * 8 + 3]) * (1.f / 128.f);
        float da = va - mua, db = vb - mub;
        float qa = da * da, qb = db * db;
        #pragma unroll
        for (int off = 16; off; off >>= 1) {
            qa += __shfl_xor_sync(0xffffffffu, qa, off);
            qb += __shfl_xor_sync(0xffffffffu, qb, off);
        }
        if ((tid & 31) == 0) { red[ua * 8 + 4 + wi] = qa; red[ub * 8 + 4 + wi] = qb; }
        __syncthreads();
        float vara = (red[ua * 8 + 4] + red[ua * 8 + 5] + red[ua * 8 + 6] + red[ua * 8 + 7]) * (1.f / 128.f);
        float varb = (red[ub * 8 + 4] + red[ub * 8 + 5] + red[ub * 8 + 6] + red[ub * 8 + 7]) * (1.f / 128.f);
        float gv = lng[fy], bv = lnb[fy];
        float* yv = (float*)(smc + OFF_Y);
        yv[ua * 132 + fy] = fmaxf(da * rsqrtf(vara + 1e-5f) * gv + bv, 0.f);
        yv[ub * 132 + fy] = fmaxf(db * rsqrtf(varb + 1e-5f) * gv + bv, 0.f);
    }
    __syncthreads();

    // MLP2 (128->256): thread = (pr = tid>>8 -> items 4pr..4pr+3, col = tid&255)
    {
        int col = tid & 255, pr = tid >> 8;
        const float* yv = (const float*)(smc + OFF_Y) + pr * 4 * 132;
        float a0 = b2[col], a1 = a0, a2 = a0, a3 = a0;
        #pragma unroll 4
        for (int f = 0; f < 128; f += 4) {
            float4 y0 = *(const float4*)&yv[0 * 132 + f];
            float4 y1 = *(const float4*)&yv[1 * 132 + f];
            float4 y2 = *(const float4*)&yv[2 * 132 + f];
            float4 y3 = *(const float4*)&yv[3 * 132 + f];
            float w0 = w2[(f + 0) * 256 + col];
            float wA = w2[(f + 1) * 256 + col];
            float wB = w2[(f + 2) * 256 + col];
            float wC = w2[(f + 3) * 256 + col];
            a0 = fmaf(y0.x, w0, fmaf(y0.y, wA, fmaf(y0.z, wB, fmaf(y0.w, wC, a0))));
            a1 = fmaf(y1.x, w0, fmaf(y1.y, wA, fmaf(y1.z, wB, fmaf(y1.w, wC, a1))));
            a2 = fmaf(y2.x, w0, fmaf(y2.y, wA, fmaf(y2.z, wB, fmaf(y2.w, wC, a2))));
            a3 = fmaf(y3.x, w0, fmaf(y3.y, wA, fmaf(y3.z, wB, fmaf(y3.w, wC, a3))));
        }
        out[(item0 + 4 * pr + 0) * 256 + col] = a0;
        out[(item0 + 4 * pr + 1) * 256 + col] = a1;
        out[(item0 + 4 * pr + 2) * 256 + col] = a2;
        out[(item0 + 4 * pr + 3) * 256 + col] = a3;
    }
}

extern "C" void kernel_launch(void* const* d_in, const int* in_sizes, int n_in,
                              void* d_out, int out_size)
{
    const float* x    = (const float*)d_in[0];
    const float* w_in = (const float*)d_in[1];
    const float* b_in = (const float*)d_in[2];
    const float* W0   = (const float*)d_in[3];
    const float* as0  = (const float*)d_in[4];
    const float* ad0  = (const float*)d_in[5];
    const float* bb0  = (const float*)d_in[6];
    const float* W1   = (const float*)d_in[7];
    const float* as1  = (const float*)d_in[8];
    const float* ad1  = (const float*)d_in[9];
    const float* bb1  = (const float*)d_in[10];
    const float* W2   = (const float*)d_in[11];
    const float* as2  = (const float*)d_in[12];
    const float* ad2  = (const float*)d_in[13];
    const float* bb2  = (const float*)d_in[14];
    const float* w1   = (const float*)d_in[15];
    const float* b1   = (const float*)d_in[16];
    const float* lng  = (const float*)d_in[17];
    const float* lnb  = (const float*)d_in[18];
    const float* w2   = (const float*)d_in[19];
    const float* b2   = (const float*)d_in[20];
    float* out = (float*)d_out;

    int B = out_size / 256;        // 16384
    int grid = B / 8;              // 8 graphs per block

    prep_kernel<<<576, 256>>>(W0, W1, W2);

    cudaFuncSetAttribute(gat_mma_kernel,
                         cudaFuncAttributeMaxDynamicSharedMemorySize, SMEM_BYTES);
    gat_mma_kernel<<<grid, 512, SMEM_BYTES>>>(
        x, w_in, b_in,
        as0, ad0, bb0, as1, ad1, bb1, as2, ad2, bb2,
        w1, b1, lng, lnb, w2, b2, out);
}

// round 17
// speedup vs baseline: 1.1881x; 1.1881x over previous
#include <cuda_runtime.h>
#include <cuda_fp16.h>
#include <cstdint>

// Fused GAT network on mma.sync.m16n8k16 (A fp16, B fp16, fp32 accum).
// 8 graphs per 512-thread block: M = 128, N = 256, K = FIN.
// R17: B operands pre-packed in mma fragment order by the prep kernel and
// loaded straight from global (L1/L2-resident) — no B smem, no staging,
// no cp.async, only 2 block barriers per layer.

#define NN 16
#define ASTRB 528         // A row stride bytes (264 halves)

// ---- shared memory byte offsets ----
#define OFF_A     0            // fp16 A tile 128 x 264 (67584 B)
#define OFF_ALPHA 67584        // alpha fp16 planes: 32 x 784 B = 25088 B
#define OFF_ASRC  92672        // 3 layers x 1024 B
#define OFF_ADST  95744        // 3 layers x 1024 B
#define OFF_WSCR  98816        // 4096 B: 16 warps x 64 floats
#define OFF_G4    102912       // 8192 B (FINAL only)
#define OFF_XS    102912       // x staging 8192 B overlays G4 (pre-layer0)
#define OFF_G     111104       // 2048 B
#define OFF_Y     113152       // 4224 B
#define OFF_RED   117376       // 256 B
#define SMEM_BYTES 117632

// B fragments, packed per layer: [ntp][k16][lane] -> uint4
// L0: 16*4*32 = 2048, L1: 16*16*32 = 8192, L2: 8192. Total 18432 uint4.
__device__ __align__(16) uint4 g_Bfrag[18432];

__device__ __forceinline__ uint32_t smem_u32(const void* p) {
    uint32_t a;
    asm("{ .reg .u64 t; cvta.to.shared.u64 t, %1; cvt.u32.u64 %0, t; }" : "=r"(a) : "l"(p));
    return a;
}

#define LDSM4(r, a) \
    asm volatile("ldmatrix.sync.aligned.m8n8.x4.shared.b16 {%0,%1,%2,%3}, [%4];" \
        : "=r"((r)[0]), "=r"((r)[1]), "=r"((r)[2]), "=r"((r)[3]) : "r"(a))

#define MOVM(dst, src) \
    asm volatile("movmatrix.sync.aligned.m8n8.trans.b16 %0, %1;" \
        : "=r"(dst) : "r"(src))

#define MMA16816F(d, a, b0, b1) \
    asm volatile("mma.sync.aligned.m16n8k16.row.col.f32.f16.f16.f32 " \
        "{%0,%1,%2,%3}, {%4,%5,%6,%7}, {%8,%9}, {%0,%1,%2,%3};" \
        : "+f"((d)[0]), "+f"((d)[1]), "+f"((d)[2]), "+f"((d)[3]) \
        : "r"((a)[0]), "r"((a)[1]), "r"((a)[2]), "r"((a)[3]), "r"(b0), "r"(b1))

__device__ __forceinline__ unsigned adjmask(int i) {
    int r = i >> 2, c = i & 3;
    unsigned m = 1u << i;
    if (c > 0) m |= 1u << (i - 1);
    if (c < 3) m |= 1u << (i + 1);
    if (r > 0) m |= 1u << (i - 4);
    if (r < 3) m |= 1u << (i + 4);
    return m;
}

// ---- weight prep: pack fp16 B fragments in mma order ----
// For layer with FIN rows: frag[((ntp*K16 + k16)*32 + l)] =
//   { h2(W[kb][n0],W[kb+1][n0]), h2(W[kb+8][n0],W[kb+9][n0]),
//     h2(W[kb][n1],W[kb+1][n1]), h2(W[kb+8][n1],W[kb+9][n1]) }
// with n0 = ntp*16 + l/4, n1 = n0+8, kb = k16*16 + (l&3)*2. W is [FIN][256].
__device__ __forceinline__ uint32_t pk2h(float a, float b) {
    __half2 h = __floats2half2_rn(a, b);
    return *(uint32_t*)&h;
}

__global__ void prep_kernel(const float* __restrict__ W0,
                            const float* __restrict__ W1,
                            const float* __restrict__ W2) {
    int i = blockIdx.x * 256 + threadIdx.x;
    if (i >= 18432) return;
    const float* W; int K16, li;
    if (i < 2048)       { W = W0; K16 = 4;  li = i; }
    else if (i < 10240) { W = W1; K16 = 16; li = i - 2048; }
    else                { W = W2; K16 = 16; li = i - 10240; }
    int l = li & 31;
    int rest = li >> 5;
    int k16 = rest % K16;
    int ntp = rest / K16;
    int n0 = ntp * 16 + (l >> 2), n1 = n0 + 8;
    int kb = k16 * 16 + (l & 3) * 2;
    uint4 o;
    o.x = pk2h(W[kb * 256 + n0],       W[(kb + 1) * 256 + n0]);
    o.y = pk2h(W[(kb + 8) * 256 + n0], W[(kb + 9) * 256 + n0]);
    o.z = pk2h(W[kb * 256 + n1],       W[(kb + 1) * 256 + n1]);
    o.w = pk2h(W[(kb + 8) * 256 + n1], W[(kb + 9) * 256 + n1]);
    g_Bfrag[i] = o;
}

// ---- one GAT layer ----
template<int K16, bool FINAL>
__device__ void gat_layer(char* smc, uint32_t smb, int tid,
                          const uint4* __restrict__ Bfrag,
                          const float* __restrict__ as_s,
                          const float* __restrict__ ad_s,
                          const float* __restrict__ bb)
{
    const int wid = tid >> 5, l = tid & 31;
    const int wr2 = wid & 3;         // row block: items 2wr2, 2wr2+1
    const int cg4 = wid >> 2;        // head: cols 64*cg4 .. +63

    uint32_t aAddr0 = smb + OFF_A + (uint32_t)((wr2 * 32 + (l & 15)) * ASTRB)
                    + (uint32_t)((l >> 4) * 16);
    uint32_t aAddr1 = aAddr0 + 16 * ASTRB;

    float d[2][8][4];
    #pragma unroll
    for (int rg = 0; rg < 2; rg++)
        #pragma unroll
        for (int nb = 0; nb < 8; nb++)
            #pragma unroll
            for (int q = 0; q < 4; q++) d[rg][nb][q] = 0.f;

    // entry: A tile written by previous epilogue / input linear
    __syncthreads();

    // mainloop: B fragments straight from global (L1/L2 resident)
    const uint4* bfr = Bfrag + ((size_t)(4 * cg4) * K16) * 32 + l;
    #pragma unroll
    for (int k16 = 0; k16 < K16; k16++) {
        uint32_t a0[4], a1[4];
        LDSM4(a0, aAddr0 + k16 * 32);
        LDSM4(a1, aAddr1 + k16 * 32);
        const uint4* bp = bfr + k16 * 32;
        #pragma unroll
        for (int j = 0; j < 4; j++) {
            uint4 bv = bp[(size_t)j * (K16 * 32)];
            MMA16816F(d[0][2 * j],     a0, bv.x, bv.y);
            MMA16816F(d[0][2 * j + 1], a0, bv.z, bv.w);
            MMA16816F(d[1][2 * j],     a1, bv.x, bv.y);
            MMA16816F(d[1][2 * j + 1], a1, bv.z, bv.w);
        }
    }
    __syncthreads();   // all A reads done before epilogue overwrites A

    // ---- in-register logits from D-fragments (head = cg4), warp-local ----
    float* wsc = (float*)(smc + OFF_WSCR) + wid * 64;
    {
        float pS[2][2] = {{0.f,0.f},{0.f,0.f}};
        float pD[2][2] = {{0.f,0.f},{0.f,0.f}};
        const float* asp = as_s + cg4 * 64;
        const float* adp = ad_s + cg4 * 64;
        int cbase = (l & 3) * 2;
        #pragma unroll
        for (int nb = 0; nb < 8; nb++) {
            int c64 = nb * 8 + cbase;
            float2 av = *(const float2*)&asp[c64];
            float2 dv = *(const float2*)&adp[c64];
            #pragma unroll
            for (int rg = 0; rg < 2; rg++) {
                pS[rg][0] = fmaf(d[rg][nb][0], av.x, fmaf(d[rg][nb][1], av.y, pS[rg][0]));
                pS[rg][1] = fmaf(d[rg][nb][2], av.x, fmaf(d[rg][nb][3], av.y, pS[rg][1]));
                pD[rg][0] = fmaf(d[rg][nb][0], dv.x, fmaf(d[rg][nb][1], dv.y, pD[rg][0]));
                pD[rg][1] = fmaf(d[rg][nb][2], dv.x, fmaf(d[rg][nb][3], dv.y, pD[rg][1]));
            }
        }
        #pragma unroll
        for (int off = 1; off <= 2; off <<= 1) {
            #pragma unroll
            for (int rg = 0; rg < 2; rg++) {
                #pragma unroll
                for (int rh = 0; rh < 2; rh++) {
                    pS[rg][rh] += __shfl_xor_sync(0xffffffffu, pS[rg][rh], off);
                    pD[rg][rh] += __shfl_xor_sync(0xffffffffu, pD[rg][rh], off);
                }
            }
        }
        if ((l & 3) == 0) {
            int n1 = l >> 2;
            #pragma unroll
            for (int rg = 0; rg < 2; rg++) {
                #pragma unroll
                for (int rh = 0; rh < 2; rh++) {
                    wsc[rg * 32 + (n1 + 8 * rh)]      = pS[rg][rh];
                    wsc[rg * 32 + 16 + (n1 + 8 * rh)] = pD[rg][rh];
                }
            }
        }
    }
    __syncwarp();

    // ---- warp-local masked softmax: lane = (uloc = l>>4, i = l&15) ----
    {
        int uloc = l >> 4, i = l & 15;
        int u = wr2 * 2 + uloc;
        float ed = wsc[uloc * 32 + 16 + i];
        unsigned m = adjmask(i);
        float eb[NN];
        float mx = -1e30f;
        #pragma unroll
        for (int j = 0; j < NN; j++) {
            eb[j] = -1e30f;
            if ((m >> j) & 1u) {
                float e = ed + wsc[uloc * 32 + j];
                e = e > 0.f ? e : 0.2f * e;
                eb[j] = e;
                mx = fmaxf(mx, e);
            }
        }
        float ssum = 0.f;
        #pragma unroll
        for (int j = 0; j < NN; j++) {
            float a = ((m >> j) & 1u) ? __expf(eb[j] - mx) : 0.f;
            eb[j] = a;
            ssum += a;
        }
        float inv = 1.f / ssum;
        __half2 hp[8];
        #pragma unroll
        for (int j2 = 0; j2 < 8; j2++)
            hp[j2] = __floats2half2_rn(eb[2 * j2] * inv, eb[2 * j2 + 1] * inv);
        char* dst = smc + OFF_ALPHA + (u * 4 + cg4) * 784 + i * 48;
        uint4 w0, w1;
        w0.x = *(uint32_t*)&hp[0]; w0.y = *(uint32_t*)&hp[1];
        w0.z = *(uint32_t*)&hp[2]; w0.w = *(uint32_t*)&hp[3];
        w1.x = *(uint32_t*)&hp[4]; w1.y = *(uint32_t*)&hp[5];
        w1.z = *(uint32_t*)&hp[6]; w1.w = *(uint32_t*)&hp[7];
        *(uint4*)dst = w0;
        *(uint4*)(dst + 16) = w1;
    }
    __syncwarp();

    // ---- aggregation on tensor cores, fully warp-local (movmatrix B) ----
    #pragma unroll
    for (int rg = 0; rg < 2; rg++) {
        int u = wr2 * 2 + rg;
        uint32_t aA = smb + OFF_ALPHA
                    + (uint32_t)((u * 4 + cg4) * 784 + (l & 15) * 48 + (l >> 4) * 16);
        uint32_t af[4];
        LDSM4(af, aA);
        float ddag[8][4];
        #pragma unroll
        for (int nb = 0; nb < 8; nb++) {
            ddag[nb][0] = ddag[nb][1] = ddag[nb][2] = ddag[nb][3] = 0.f;
            __half2 h01 = __floats2half2_rn(d[rg][nb][0], d[rg][nb][1]);
            __half2 h23 = __floats2half2_rn(d[rg][nb][2], d[rg][nb][3]);
            uint32_t b0, b1;
            MOVM(b0, *(uint32_t*)&h01);
            MOVM(b1, *(uint32_t*)&h23);
            MMA16816F(ddag[nb], af, b0, b1);
        }
        if (FINAL) {
            #pragma unroll
            for (int nb = 0; nb < 8; nb++) {
                float pc0 = ddag[nb][0] + ddag[nb][2];
                float pc1 = ddag[nb][1] + ddag[nb][3];
                #pragma unroll
                for (int off = 4; off <= 16; off <<= 1) {
                    pc0 += __shfl_xor_sync(0xffffffffu, pc0, off);
                    pc1 += __shfl_xor_sync(0xffffffffu, pc1, off);
                }
                if (l < 4)
                    *(float2*)((float*)(smc + OFF_G4) + u * 256 + cg4 * 64 + nb * 8 + l * 2)
                        = make_float2(pc0, pc1);
            }
        } else {
            __half* ab = (__half*)(smc + OFF_A);
            int r0 = u * 16 + (l >> 2);
            #pragma unroll
            for (int nb = 0; nb < 8; nb++) {
                int cn = cg4 * 64 + nb * 8 + (l & 3) * 2;
                float2 bv = *(const float2*)&bb[cn];
                float v0 = fmaxf(ddag[nb][0] + bv.x, 0.f);
                float v1 = fmaxf(ddag[nb][1] + bv.y, 0.f);
                float v2 = fmaxf(ddag[nb][2] + bv.x, 0.f);
                float v3 = fmaxf(ddag[nb][3] + bv.y, 0.f);
                *(__half2*)&ab[r0 * 264 + cn]       = __floats2half2_rn(v0, v1);
                *(__half2*)&ab[(r0 + 8) * 264 + cn] = __floats2half2_rn(v2, v3);
            }
        }
    }
    if (FINAL) __syncthreads();
    // non-FINAL: next layer's entry __syncthreads orders the A writeback
}

__global__ void __launch_bounds__(512, 1) gat_mma_kernel(
    const float* __restrict__ x,
    const float* __restrict__ w_in, const float* __restrict__ b_in,
    const float* __restrict__ as0, const float* __restrict__ ad0,
    const float* __restrict__ bb0,
    const float* __restrict__ as1, const float* __restrict__ ad1,
    const float* __restrict__ bb1,
    const float* __restrict__ as2, const float* __restrict__ ad2,
    const float* __restrict__ bb2,
    const float* __restrict__ w1, const float* __restrict__ b1,
    const float* __restrict__ lng, const float* __restrict__ lnb,
    const float* __restrict__ w2, const float* __restrict__ b2,
    float* __restrict__ out)
{
    extern __shared__ char smc[];
    uint32_t smb = smem_u32(smc);
    int tid = threadIdx.x;
    long item0 = (long)blockIdx.x * 8;

    // stage x (overlays G4) + all 3 layers' attention vectors
    float* xs = (float*)(smc + OFF_XS);
    #pragma unroll
    for (int q = 0; q < 4; q++)
        xs[q * 512 + tid] = x[item0 * 256 + q * 512 + tid];
    {
        float* AS = (float*)(smc + OFF_ASRC);
        float* AD = (float*)(smc + OFF_ADST);
        if (tid < 256) {
            AS[tid]        = as0[tid];
            AS[256 + tid]  = as1[tid];
            AS[512 + tid]  = as2[tid];
        } else {
            int t2 = tid - 256;
            AD[t2]         = ad0[t2];
            AD[256 + t2]   = ad1[t2];
            AD[512 + t2]   = ad2[t2];
        }
    }
    __syncthreads();

    // input linear -> A (fp16), thread = (u = tid>>6, f = tid&63)
    {
        int u = tid >> 6, f = tid & 63;
        const float* xu = xs + u * 256;
        float acc[NN];
        #pragma unroll
        for (int nn = 0; nn < NN; nn++) acc[nn] = 0.f;
        #pragma unroll
        for (int c = 0; c < 16; c++) {
            float wv = w_in[c * 64 + f];
            #pragma unroll
            for (int nn = 0; nn < NN; nn++)
                acc[nn] = fmaf(xu[c * 16 + nn], wv, acc[nn]);
        }
        float bv = b_in[f];
        __half* ab = (__half*)(smc + OFF_A);
        #pragma unroll
        for (int nn = 0; nn < NN; nn++) {
            float vv = fmaxf(acc[nn] + bv, 0.f);
            ab[(u * 16 + nn) * 264 + f] = __float2half_rn(vv);
        }
    }
    // layer entry syncthreads orders A writes

    const float* AS = (const float*)(smc + OFF_ASRC);
    const float* AD = (const float*)(smc + OFF_ADST);
    gat_layer<4,  false>(smc, smb, tid, g_Bfrag,         AS,       AD,       bb0);
    gat_layer<16, false>(smc, smb, tid, g_Bfrag + 2048,  AS + 256, AD + 256, bb1);
    gat_layer<16, true >(smc, smb, tid, g_Bfrag + 10240, AS + 512, AD + 512, bb2);

    // pooled g[c] = mean over nodes+heads + bb2
    {
        int u = tid >> 6, cc = tid & 63;
        const float* g4 = (const float*)(smc + OFF_G4) + u * 256;
        float sg = g4[cc] + g4[64 + cc] + g4[128 + cc] + g4[192 + cc];
        ((float*)(smc + OFF_G))[u * 64 + cc] = sg * (1.0f / 64.0f) + bb2[cc];
    }
    __syncthreads();

    // MLP1 (64->128) + LN + relu; thread covers items up, up+4
    {
        int fy = tid & 127, up = tid >> 7;
        int ua = up, ub = up + 4;
        const float* ga_ = (const float*)(smc + OFF_G) + ua * 64;
        const float* gb_ = (const float*)(smc + OFF_G) + ub * 64;
        float va = b1[fy], vb = va;
        #pragma unroll 4
        for (int c = 0; c < 64; c += 4) {
            float4 ga = *(const float4*)&ga_[c];
            float4 gb = *(const float4*)&gb_[c];
            float w0 = w1[(c + 0) * 128 + fy];
            float wA = w1[(c + 1) * 128 + fy];
            float wB = w1[(c + 2) * 128 + fy];
            float wC = w1[(c + 3) * 128 + fy];
            va = fmaf(ga.x, w0, fmaf(ga.y, wA, fmaf(ga.z, wB, fmaf(ga.w, wC, va))));
            vb = fmaf(gb.x, w0, fmaf(gb.y, wA, fmaf(gb.z, wB, fmaf(gb.w, wC, vb))));
        }
        float* red = (float*)(smc + OFF_RED);
        float sa = va, sb = vb;
        #pragma unroll
        for (int off = 16; off; off >>= 1) {
            sa += __shfl_xor_sync(0xffffffffu, sa, off);
            sb += __shfl_xor_sync(0xffffffffu, sb, off);
        }
        int wi = (tid >> 5) & 3;
        if ((tid & 31) == 0) { red[ua * 8 + wi] = sa; red[ub * 8 + wi] = sb; }
        __syncthreads();
        float mua = (red[ua * 8] + red[ua * 8 + 1] + red[ua * 8 + 2] + red[ua * 8 + 3]) * (1.f / 128.f);
        float mub = (red[ub * 8] + red[ub * 8 + 1] + red[ub * 8 + 2] + red[ub * 8 + 3]) * (1.f / 128.f);
        float da = va - mua, db = vb - mub;
        float qa = da * da, qb = db * db;
        #pragma unroll
        for (int off = 16; off; off >>= 1) {
            qa += __shfl_xor_sync(0xffffffffu, qa, off);
            qb += __shfl_xor_sync(0xffffffffu, qb, off);
        }
        if ((tid & 31) == 0) { red[ua * 8 + 4 + wi] = qa; red[ub * 8 + 4 + wi] = qb; }
        __syncthreads();
        float vara = (red[ua * 8 + 4] + red[ua * 8 + 5] + red[ua * 8 + 6] + red[ua * 8 + 7]) * (1.f / 128.f);
        float varb = (red[ub * 8 + 4] + red[ub * 8 + 5] + red[ub * 8 + 6] + red[ub * 8 + 7]) * (1.f / 128.f);
        float gv = lng[fy], bv = lnb[fy];
        float* yv = (float*)(smc + OFF_Y);
        yv[ua * 132 + fy] = fmaxf(da * rsqrtf(vara + 1e-5f) * gv + bv, 0.f);
        yv[ub * 132 + fy] = fmaxf(db * rsqrtf(varb + 1e-5f) * gv + bv, 0.f);
    }
    __syncthreads();

    // MLP2 (128->256): thread = (pr = tid>>8 -> items 4pr..4pr+3, col = tid&255)
    {
        int col = tid & 255, pr = tid >> 8;
        const float* yv = (const float*)(smc + OFF_Y) + pr * 4 * 132;
        float a0 = b2[col], a1 = a0, a2 = a0, a3 = a0;
        #pragma unroll 4
        for (int f = 0; f < 128; f += 4) {
            float4 y0 = *(const float4*)&yv[0 * 132 + f];
            float4 y1 = *(const float4*)&yv[1 * 132 + f];
            float4 y2 = *(const float4*)&yv[2 * 132 + f];
            float4 y3 = *(const float4*)&yv[3 * 132 + f];
            float w0 = w2[(f + 0) * 256 + col];
            float wA = w2[(f + 1) * 256 + col];
            float wB = w2[(f + 2) * 256 + col];
            float wC = w2[(f + 3) * 256 + col];
            a0 = fmaf(y0.x, w0, fmaf(y0.y, wA, fmaf(y0.z, wB, fmaf(y0.w, wC, a0))));
            a1 = fmaf(y1.x, w0, fmaf(y1.y, wA, fmaf(y1.z, wB, fmaf(y1.w, wC, a1))));
            a2 = fmaf(y2.x, w0, fmaf(y2.y, wA, fmaf(y2.z, wB, fmaf(y2.w, wC, a2))));
            a3 = fmaf(y3.x, w0, fmaf(y3.y, wA, fmaf(y3.z, wB, fmaf(y3.w, wC, a3))));
        }
        out[(item0 + 4 * pr + 0) * 256 + col] = a0;
        out[(item0 + 4 * pr + 1) * 256 + col] = a1;
        out[(item0 + 4 * pr + 2) * 256 + col] = a2;
        out[(item0 + 4 * pr + 3) * 256 + col] = a3;
    }
}

extern "C" void kernel_launch(void* const* d_in, const int* in_sizes, int n_in,
                              void* d_out, int out_size)
{
    const float* x    = (const float*)d_in[0];
    const float* w_in = (const float*)d_in[1];
    const float* b_in = (const float*)d_in[2];
    const float* W0   = (const float*)d_in[3];
    const float* as0  = (const float*)d_in[4];
    const float* ad0  = (const float*)d_in[5];
    const float* bb0  = (const float*)d_in[6];
    const float* W1   = (const float*)d_in[7];
    const float* as1  = (const float*)d_in[8];
    const float* ad1  = (const float*)d_in[9];
    const float* bb1  = (const float*)d_in[10];
    const float* W2   = (const float*)d_in[11];
    const float* as2  = (const float*)d_in[12];
    const float* ad2  = (const float*)d_in[13];
    const float* bb2  = (const float*)d_in[14];
    const float* w1   = (const float*)d_in[15];
    const float* b1   = (const float*)d_in[16];
    const float* lng  = (const float*)d_in[17];
    const float* lnb  = (const float*)d_in[18];
    const float* w2   = (const float*)d_in[19];
    const float* b2   = (const float*)d_in[20];
    float* out = (float*)d_out;

    int B = out_size / 256;        // 16384
    int grid = B / 8;              // 8 graphs per block

    prep_kernel<<<72, 256>>>(W0, W1, W2);

    cudaFuncSetAttribute(gat_mma_kernel,
                         cudaFuncAttributeMaxDynamicSharedMemorySize, SMEM_BYTES);
    gat_mma_kernel<<<grid, 512, SMEM_BYTES>>>(
        x, w_in, b_in,
        as0, ad0, bb0, as1, ad1, bb1, as2, ad2, bb2,
        w1, b1, lng, lnb, w2, b2, out);
}